// round 5
// baseline (speedup 1.0000x reference)
#include <cuda_runtime.h>
#include <cstdint>

// GCN block: agg = D_in^-1/2 * A * (D_out^-1/2 * x); h = agg@W + b;
// h = nodenorm(h); out = relu(h) + x.   N=100000, E=1600000, D=128.
//
// Round 5: R4 pipeline + (a) self-zeroing counters (no zero kernel, 4 launches,
// gemm lands in the profiled slot), (b) GEMM with packed fma.rn.f32x2,
// 8 rows/warp so the smem crossbar stays under the FMA2 floor.

#define DIMF 128
#define MAXN 100352
#define BSTRIDE 96          // bucket capacity per dst row (Poisson(16) tail-safe)

// Device globals are zero-initialized at module load; kernels below restore
// counters to zero at the end of every run, so each replay starts clean.
__device__ int   g_cnt[MAXN];            // in-degree / bucket cursor
__device__ int   g_outdeg[MAXN];
__device__ int   g_bucket[MAXN * BSTRIDE];
__device__ float g_norm_src[MAXN];
__device__ float g_norm_dst[MAXN];
__device__ float g_agg[MAXN * DIMF];

// ---------------------------------------------------------------------------
// K0: fused degree histogram + bucket scatter (one pass over edges, int4)
// ---------------------------------------------------------------------------
__device__ __forceinline__ void scatter_one(int s, int d) {
    int pos = atomicAdd(&g_cnt[d], 1);
    if (pos < BSTRIDE) g_bucket[d * BSTRIDE + pos] = s;
    atomicAdd(&g_outdeg[s], 1);          // no return use -> RED
}

__global__ void scatter_kernel(const int* __restrict__ src,
                               const int* __restrict__ dst, int E) {
    int t = blockIdx.x * blockDim.x + threadIdx.x;
    int base = t * 4;
    if (base + 3 < E) {
        int4 s4 = reinterpret_cast<const int4*>(src)[t];
        int4 d4 = reinterpret_cast<const int4*>(dst)[t];
        scatter_one(s4.x, d4.x);
        scatter_one(s4.y, d4.y);
        scatter_one(s4.z, d4.z);
        scatter_one(s4.w, d4.w);
    } else {
        for (int e = base; e < E; e++) scatter_one(src[e], dst[e]);
    }
}

// ---------------------------------------------------------------------------
// K1: norms from degrees
// ---------------------------------------------------------------------------
__global__ void norm_kernel(int N) {
    int i = blockIdx.x * blockDim.x + threadIdx.x;
    if (i < N) {
        g_norm_src[i] = rsqrtf(fmaxf((float)g_outdeg[i], 1.0f));
        g_norm_dst[i] = rsqrtf(fmaxf((float)g_cnt[i], 1.0f));
    }
}

// ---------------------------------------------------------------------------
// K2: gather — one warp per dst row. agg[d] = nd * sum_s norm_src[s]*x[s].
// Lane 0 re-zeroes g_cnt[row] after use (next run's scatter needs zeros).
// ---------------------------------------------------------------------------
__global__ void gather_kernel(const float4* __restrict__ x4, int N) {
    int row = (blockIdx.x * blockDim.x + threadIdx.x) >> 5;
    if (row >= N) return;
    int lane = threadIdx.x & 31;
    int c = g_cnt[row];
    if (lane == 0) g_cnt[row] = 0;
    if (c > BSTRIDE) c = BSTRIDE;
    const int* bk = g_bucket + row * BSTRIDE;
    float4 acc = {0.f, 0.f, 0.f, 0.f};
    int i = 0;
    for (; i + 3 < c; i += 4) {
        int s0 = bk[i], s1 = bk[i + 1], s2 = bk[i + 2], s3 = bk[i + 3];
        float n0 = g_norm_src[s0];
        float n1 = g_norm_src[s1];
        float n2 = g_norm_src[s2];
        float n3 = g_norm_src[s3];
        float4 v0 = x4[s0 * (DIMF / 4) + lane];
        float4 v1 = x4[s1 * (DIMF / 4) + lane];
        float4 v2 = x4[s2 * (DIMF / 4) + lane];
        float4 v3 = x4[s3 * (DIMF / 4) + lane];
        acc.x = fmaf(v0.x, n0, acc.x); acc.y = fmaf(v0.y, n0, acc.y);
        acc.z = fmaf(v0.z, n0, acc.z); acc.w = fmaf(v0.w, n0, acc.w);
        acc.x = fmaf(v1.x, n1, acc.x); acc.y = fmaf(v1.y, n1, acc.y);
        acc.z = fmaf(v1.z, n1, acc.z); acc.w = fmaf(v1.w, n1, acc.w);
        acc.x = fmaf(v2.x, n2, acc.x); acc.y = fmaf(v2.y, n2, acc.y);
        acc.z = fmaf(v2.z, n2, acc.z); acc.w = fmaf(v2.w, n2, acc.w);
        acc.x = fmaf(v3.x, n3, acc.x); acc.y = fmaf(v3.y, n3, acc.y);
        acc.z = fmaf(v3.z, n3, acc.z); acc.w = fmaf(v3.w, n3, acc.w);
    }
    for (; i < c; i++) {
        int s = bk[i];
        float ns = g_norm_src[s];
        float4 v = x4[s * (DIMF / 4) + lane];
        acc.x = fmaf(v.x, ns, acc.x); acc.y = fmaf(v.y, ns, acc.y);
        acc.z = fmaf(v.z, ns, acc.z); acc.w = fmaf(v.w, ns, acc.w);
    }
    float nd = g_norm_dst[row];
    acc.x *= nd; acc.y *= nd; acc.z *= nd; acc.w *= nd;
    reinterpret_cast<float4*>(g_agg)[row * (DIMF / 4) + lane] = acc;
}

// ---------------------------------------------------------------------------
// K3: GEMM + NodeNorm + relu + residual with packed fma.rn.f32x2.
// Persistent blocks, W in smem, 8 rows/warp, lane l owns cols 4l..4l+3
// (two f32x2 pairs). Also grid-stride zeroes g_outdeg for the next run.
// ---------------------------------------------------------------------------
#define ROWS_PW 8
#define GEMM_SMEM_BYTES ((DIMF * DIMF + 8 * ROWS_PW * DIMF) * 4)   // 98304

__device__ __forceinline__ unsigned long long bcast2(float c) {
    unsigned long long r;
    asm("mov.b64 %0, {%1, %1};" : "=l"(r) : "f"(c));
    return r;
}
__device__ __forceinline__ void fma2(unsigned long long& acc,
                                     unsigned long long a, unsigned long long b) {
    asm("fma.rn.f32x2 %0, %1, %2, %0;" : "+l"(acc) : "l"(a), "l"(b));
}
__device__ __forceinline__ float2 unpack2(unsigned long long v) {
    float2 r;
    asm("mov.b64 {%0, %1}, %2;" : "=f"(r.x), "=f"(r.y) : "l"(v));
    return r;
}

__global__ __launch_bounds__(256, 2)
void gemm_norm_kernel(const float4* __restrict__ x4,
                      const float* __restrict__ weight,
                      const float* __restrict__ bias,
                      float4* __restrict__ out4, int N) {
    extern __shared__ float sh[];
    float* Wsh = sh;                          // 128x128 f32 (64KB)
    float* rowbuf = sh + DIMF * DIMF;         // 8 warps * 8 rows * 128 f32 (32KB)

    // zero g_outdeg for the next run (consumed already by norm_kernel)
    for (int i = blockIdx.x * blockDim.x + threadIdx.x; i < N;
         i += gridDim.x * blockDim.x)
        g_outdeg[i] = 0;

    {
        const float4* Wg = reinterpret_cast<const float4*>(weight);
        float4* Ws = reinterpret_cast<float4*>(Wsh);
        for (int i = threadIdx.x; i < DIMF * DIMF / 4; i += blockDim.x)
            Ws[i] = Wg[i];
    }
    __syncthreads();

    const int warp = threadIdx.x >> 5;
    const int lane = threadIdx.x & 31;
    const int nwarps = (gridDim.x * blockDim.x) >> 5;
    const int gwarp = (blockIdx.x * blockDim.x + threadIdx.x) >> 5;
    float* myrow = rowbuf + warp * (ROWS_PW * DIMF);
    const ulonglong2* Wv2 = reinterpret_cast<const ulonglong2*>(Wsh);
    const float4 bv = reinterpret_cast<const float4*>(bias)[lane];
    const float4* agg4 = reinterpret_cast<const float4*>(g_agg);

    for (int base = gwarp * ROWS_PW; base < N; base += nwarps * ROWS_PW) {
        #pragma unroll
        for (int r = 0; r < ROWS_PW; r++) {
            int row = base + r;
            if (row < N)
                reinterpret_cast<float4*>(myrow + r * DIMF)[lane] =
                    agg4[row * (DIMF / 4) + lane];
        }
        __syncwarp();

        // acc[r][p]: p0 = cols {4l,4l+1}, p1 = cols {4l+2,4l+3}
        unsigned long long acc[ROWS_PW][2] = {};

        #pragma unroll 2
        for (int k4 = 0; k4 < DIMF / 4; k4++) {
            float4 a[ROWS_PW];
            #pragma unroll
            for (int r = 0; r < ROWS_PW; r++)
                a[r] = reinterpret_cast<const float4*>(myrow + r * DIMF)[k4];
            #pragma unroll
            for (int j = 0; j < 4; j++) {
                ulonglong2 w = Wv2[(k4 * 4 + j) * (DIMF / 4) + lane];
                #pragma unroll
                for (int r = 0; r < ROWS_PW; r++) {
                    float cj = reinterpret_cast<const float*>(&a[r])[j];
                    unsigned long long c = bcast2(cj);
                    fma2(acc[r][0], c, w.x);
                    fma2(acc[r][1], c, w.y);
                }
            }
        }

        #pragma unroll
        for (int r = 0; r < ROWS_PW; r++) {
            int row = base + r;
            if (row >= N) break;
            float2 h01 = unpack2(acc[r][0]);
            float2 h23 = unpack2(acc[r][1]);
            float4 h = make_float4(h01.x, h01.y, h23.x, h23.y);
            h.x += bv.x; h.y += bv.y; h.z += bv.z; h.w += bv.w;
            float s  = h.x + h.y + h.z + h.w;
            float ss = h.x * h.x + h.y * h.y + h.z * h.z + h.w * h.w;
            #pragma unroll
            for (int off = 16; off > 0; off >>= 1) {
                s  += __shfl_xor_sync(0xffffffffu, s, off);
                ss += __shfl_xor_sync(0xffffffffu, ss, off);
            }
            float mean = s * (1.0f / DIMF);
            float var = ss * (1.0f / DIMF) - mean * mean;
            float inv = rsqrtf(var + 1e-5f);
            float4 xv = x4[row * (DIMF / 4) + lane];
            float4 o;
            o.x = fmaxf((h.x - mean) * inv, 0.f) + xv.x;
            o.y = fmaxf((h.y - mean) * inv, 0.f) + xv.y;
            o.z = fmaxf((h.z - mean) * inv, 0.f) + xv.z;
            o.w = fmaxf((h.w - mean) * inv, 0.f) + xv.w;
            out4[row * (DIMF / 4) + lane] = o;
        }
        __syncwarp();
    }
}

// ---------------------------------------------------------------------------
extern "C" void kernel_launch(void* const* d_in, const int* in_sizes, int n_in,
                              void* d_out, int out_size) {
    const float* x      = (const float*)d_in[0];
    const float* weight = (const float*)d_in[1];
    const float* bias   = (const float*)d_in[2];
    const int*   src    = (const int*)d_in[3];
    const int*   dst    = (const int*)d_in[4];
    float* out = (float*)d_out;

    const int N = in_sizes[0] / DIMF;
    const int E = in_sizes[3];
    if (N > MAXN) return;

    cudaFuncSetAttribute(gemm_norm_kernel,
                         cudaFuncAttributeMaxDynamicSharedMemorySize,
                         GEMM_SMEM_BYTES);

    const float4* x4 = (const float4*)x;

    scatter_kernel<<<(E / 4 + 255) / 256 + 1, 256>>>(src, dst, E);   // idx 0
    norm_kernel<<<(N + 255) / 256, 256>>>(N);                        // idx 1
    gather_kernel<<<(N + 7) / 8, 256>>>(x4, N);                      // idx 2
    gemm_norm_kernel<<<296, 256, GEMM_SMEM_BYTES>>>(x4, weight, bias,
                                                    (float4*)out, N); // idx 3 (profiled)
}

// round 6
// speedup vs baseline: 2.2594x; 2.2594x over previous
#include <cuda_runtime.h>
#include <cstdint>

// GCN block: agg = D_in^-1/2 * A * (D_out^-1/2 * x); h = agg@W + b;
// h = nodenorm(h); out = relu(h) + x.   N=100000, E=1600000, D=128.
//
// Round 6: R4 pipeline VERBATIM (zero/scatter/norm/gather, 190.5us proven),
// only the GEMM swapped to the fma.rn.f32x2 version ncu measured at 90us.

#define DIMF 128
#define MAXN 100352
#define BSTRIDE 96          // bucket capacity per dst row (Poisson(16) tail-safe)

__device__ int   g_cnt[MAXN];            // in-degree / bucket cursor
__device__ int   g_outdeg[MAXN];
__device__ int   g_bucket[MAXN * BSTRIDE];
__device__ float g_norm_src[MAXN];
__device__ float g_norm_dst[MAXN];
__device__ float g_agg[MAXN * DIMF];

// ---------------------------------------------------------------------------
// K0: zero counters
// ---------------------------------------------------------------------------
__global__ void zero_kernel(int N) {
    int i = blockIdx.x * blockDim.x + threadIdx.x;
    if (i < N) { g_cnt[i] = 0; g_outdeg[i] = 0; }
}

// ---------------------------------------------------------------------------
// K1: fused degree histogram + bucket scatter (one pass over edges, int4)
// ---------------------------------------------------------------------------
__device__ __forceinline__ void scatter_one(int s, int d) {
    int pos = atomicAdd(&g_cnt[d], 1);
    if (pos < BSTRIDE) g_bucket[d * BSTRIDE + pos] = s;
    atomicAdd(&g_outdeg[s], 1);          // no return use -> RED
}

__global__ void scatter_kernel(const int* __restrict__ src,
                               const int* __restrict__ dst, int E) {
    int t = blockIdx.x * blockDim.x + threadIdx.x;
    int base = t * 4;
    if (base + 3 < E) {
        int4 s4 = reinterpret_cast<const int4*>(src)[t];
        int4 d4 = reinterpret_cast<const int4*>(dst)[t];
        scatter_one(s4.x, d4.x);
        scatter_one(s4.y, d4.y);
        scatter_one(s4.z, d4.z);
        scatter_one(s4.w, d4.w);
    } else {
        for (int e = base; e < E; e++) scatter_one(src[e], dst[e]);
    }
}

// ---------------------------------------------------------------------------
// K2: norms from degrees
// ---------------------------------------------------------------------------
__global__ void norm_kernel(int N) {
    int i = blockIdx.x * blockDim.x + threadIdx.x;
    if (i < N) {
        g_norm_src[i] = rsqrtf(fmaxf((float)g_outdeg[i], 1.0f));
        g_norm_dst[i] = rsqrtf(fmaxf((float)g_cnt[i], 1.0f));
    }
}

// ---------------------------------------------------------------------------
// K3: gather — one warp per dst row. agg[d] = nd * sum_s norm_src[s]*x[s]
// ---------------------------------------------------------------------------
__global__ void gather_kernel(const float4* __restrict__ x4, int N) {
    int row = (blockIdx.x * blockDim.x + threadIdx.x) >> 5;
    if (row >= N) return;
    int lane = threadIdx.x & 31;
    int c = g_cnt[row];
    if (c > BSTRIDE) c = BSTRIDE;
    const int* bk = g_bucket + row * BSTRIDE;
    float4 acc = {0.f, 0.f, 0.f, 0.f};
    int i = 0;
    for (; i + 3 < c; i += 4) {
        int s0 = bk[i], s1 = bk[i + 1], s2 = bk[i + 2], s3 = bk[i + 3];
        float n0 = g_norm_src[s0];
        float n1 = g_norm_src[s1];
        float n2 = g_norm_src[s2];
        float n3 = g_norm_src[s3];
        float4 v0 = x4[s0 * (DIMF / 4) + lane];
        float4 v1 = x4[s1 * (DIMF / 4) + lane];
        float4 v2 = x4[s2 * (DIMF / 4) + lane];
        float4 v3 = x4[s3 * (DIMF / 4) + lane];
        acc.x = fmaf(v0.x, n0, acc.x); acc.y = fmaf(v0.y, n0, acc.y);
        acc.z = fmaf(v0.z, n0, acc.z); acc.w = fmaf(v0.w, n0, acc.w);
        acc.x = fmaf(v1.x, n1, acc.x); acc.y = fmaf(v1.y, n1, acc.y);
        acc.z = fmaf(v1.z, n1, acc.z); acc.w = fmaf(v1.w, n1, acc.w);
        acc.x = fmaf(v2.x, n2, acc.x); acc.y = fmaf(v2.y, n2, acc.y);
        acc.z = fmaf(v2.z, n2, acc.z); acc.w = fmaf(v2.w, n2, acc.w);
        acc.x = fmaf(v3.x, n3, acc.x); acc.y = fmaf(v3.y, n3, acc.y);
        acc.w = fmaf(v3.w, n3, acc.w); acc.z = fmaf(v3.z, n3, acc.z);
    }
    for (; i < c; i++) {
        int s = bk[i];
        float ns = g_norm_src[s];
        float4 v = x4[s * (DIMF / 4) + lane];
        acc.x = fmaf(v.x, ns, acc.x); acc.y = fmaf(v.y, ns, acc.y);
        acc.z = fmaf(v.z, ns, acc.z); acc.w = fmaf(v.w, ns, acc.w);
    }
    float nd = g_norm_dst[row];
    acc.x *= nd; acc.y *= nd; acc.z *= nd; acc.w *= nd;
    reinterpret_cast<float4*>(g_agg)[row * (DIMF / 4) + lane] = acc;
}

// ---------------------------------------------------------------------------
// K4: GEMM + NodeNorm + relu + residual, packed fma.rn.f32x2 (measured 90us).
// Persistent blocks, W in smem, 8 rows/warp, lane l owns cols 4l..4l+3.
// ---------------------------------------------------------------------------
#define ROWS_PW 8
#define GEMM_SMEM_BYTES ((DIMF * DIMF + 8 * ROWS_PW * DIMF) * 4)   // 98304

__device__ __forceinline__ unsigned long long bcast2(float c) {
    unsigned long long r;
    asm("mov.b64 %0, {%1, %1};" : "=l"(r) : "f"(c));
    return r;
}
__device__ __forceinline__ void fma2(unsigned long long& acc,
                                     unsigned long long a, unsigned long long b) {
    asm("fma.rn.f32x2 %0, %1, %2, %0;" : "+l"(acc) : "l"(a), "l"(b));
}
__device__ __forceinline__ float2 unpack2(unsigned long long v) {
    float2 r;
    asm("mov.b64 {%0, %1}, %2;" : "=f"(r.x), "=f"(r.y) : "l"(v));
    return r;
}

__global__ __launch_bounds__(256, 2)
void gemm_norm_kernel(const float4* __restrict__ x4,
                      const float* __restrict__ weight,
                      const float* __restrict__ bias,
                      float4* __restrict__ out4, int N) {
    extern __shared__ float sh[];
    float* Wsh = sh;                          // 128x128 f32 (64KB)
    float* rowbuf = sh + DIMF * DIMF;         // 8 warps * 8 rows * 128 f32 (32KB)

    {
        const float4* Wg = reinterpret_cast<const float4*>(weight);
        float4* Ws = reinterpret_cast<float4*>(Wsh);
        for (int i = threadIdx.x; i < DIMF * DIMF / 4; i += blockDim.x)
            Ws[i] = Wg[i];
    }
    __syncthreads();

    const int warp = threadIdx.x >> 5;
    const int lane = threadIdx.x & 31;
    const int nwarps = (gridDim.x * blockDim.x) >> 5;
    const int gwarp = (blockIdx.x * blockDim.x + threadIdx.x) >> 5;
    float* myrow = rowbuf + warp * (ROWS_PW * DIMF);
    const ulonglong2* Wv2 = reinterpret_cast<const ulonglong2*>(Wsh);
    const float4 bv = reinterpret_cast<const float4*>(bias)[lane];
    const float4* agg4 = reinterpret_cast<const float4*>(g_agg);

    for (int base = gwarp * ROWS_PW; base < N; base += nwarps * ROWS_PW) {
        #pragma unroll
        for (int r = 0; r < ROWS_PW; r++) {
            int row = base + r;
            if (row < N)
                reinterpret_cast<float4*>(myrow + r * DIMF)[lane] =
                    agg4[row * (DIMF / 4) + lane];
        }
        __syncwarp();

        // acc[r][p]: p0 = cols {4l,4l+1}, p1 = cols {4l+2,4l+3}
        unsigned long long acc[ROWS_PW][2] = {};

        #pragma unroll 2
        for (int k4 = 0; k4 < DIMF / 4; k4++) {
            float4 a[ROWS_PW];
            #pragma unroll
            for (int r = 0; r < ROWS_PW; r++)
                a[r] = reinterpret_cast<const float4*>(myrow + r * DIMF)[k4];
            #pragma unroll
            for (int j = 0; j < 4; j++) {
                ulonglong2 w = Wv2[(k4 * 4 + j) * (DIMF / 4) + lane];
                #pragma unroll
                for (int r = 0; r < ROWS_PW; r++) {
                    float cj = reinterpret_cast<const float*>(&a[r])[j];
                    unsigned long long c = bcast2(cj);
                    fma2(acc[r][0], c, w.x);
                    fma2(acc[r][1], c, w.y);
                }
            }
        }

        #pragma unroll
        for (int r = 0; r < ROWS_PW; r++) {
            int row = base + r;
            if (row >= N) break;
            float2 h01 = unpack2(acc[r][0]);
            float2 h23 = unpack2(acc[r][1]);
            float4 h = make_float4(h01.x, h01.y, h23.x, h23.y);
            h.x += bv.x; h.y += bv.y; h.z += bv.z; h.w += bv.w;
            float s  = h.x + h.y + h.z + h.w;
            float ss = h.x * h.x + h.y * h.y + h.z * h.z + h.w * h.w;
            #pragma unroll
            for (int off = 16; off > 0; off >>= 1) {
                s  += __shfl_xor_sync(0xffffffffu, s, off);
                ss += __shfl_xor_sync(0xffffffffu, ss, off);
            }
            float mean = s * (1.0f / DIMF);
            float var = ss * (1.0f / DIMF) - mean * mean;
            float inv = rsqrtf(var + 1e-5f);
            float4 xv = x4[row * (DIMF / 4) + lane];
            float4 o;
            o.x = fmaxf((h.x - mean) * inv, 0.f) + xv.x;
            o.y = fmaxf((h.y - mean) * inv, 0.f) + xv.y;
            o.z = fmaxf((h.z - mean) * inv, 0.f) + xv.z;
            o.w = fmaxf((h.w - mean) * inv, 0.f) + xv.w;
            out4[row * (DIMF / 4) + lane] = o;
        }
        __syncwarp();
    }
}

// ---------------------------------------------------------------------------
extern "C" void kernel_launch(void* const* d_in, const int* in_sizes, int n_in,
                              void* d_out, int out_size) {
    const float* x      = (const float*)d_in[0];
    const float* weight = (const float*)d_in[1];
    const float* bias   = (const float*)d_in[2];
    const int*   src    = (const int*)d_in[3];
    const int*   dst    = (const int*)d_in[4];
    float* out = (float*)d_out;

    const int N = in_sizes[0] / DIMF;
    const int E = in_sizes[3];
    if (N > MAXN) return;

    cudaFuncSetAttribute(gemm_norm_kernel,
                         cudaFuncAttributeMaxDynamicSharedMemorySize,
                         GEMM_SMEM_BYTES);

    const float4* x4 = (const float4*)x;

    zero_kernel<<<(N + 255) / 256, 256>>>(N);                        // idx 0
    scatter_kernel<<<(E / 4 + 255) / 256 + 1, 256>>>(src, dst, E);   // idx 1
    norm_kernel<<<(N + 255) / 256, 256>>>(N);                        // idx 2
    gather_kernel<<<(N + 7) / 8, 256>>>(x4, N);                      // idx 3
    gemm_norm_kernel<<<296, 256, GEMM_SMEM_BYTES>>>(x4, weight, bias,
                                                    (float4*)out, N); // idx 4
}